// round 2
// baseline (speedup 1.0000x reference)
#include <cuda_runtime.h>
#include <cuda_bf16.h>
#include <math.h>

// ---------------- problem constants ----------------
#define BATCH 32
#define SEQ   197          // 14*14 + 1
#define MTOK  (BATCH*SEQ)  // 6304
#define HID   768
#define NH    12
#define DH    64
#define INTER 3072
#define NLAYER 12
#define NCLS  1000
#define GP    14
#define PSZ   16
#define IMG   224
#define MPATCH (BATCH*GP*GP)   // 6272

// ---------------- scratch (device globals; no cudaMalloc allowed) ----------------
__device__ float g_h  [MTOK*HID];
__device__ float g_hn [MTOK*HID];
__device__ float g_q  [MTOK*HID];
__device__ float g_k  [MTOK*HID];
__device__ float g_v  [MTOK*HID];
__device__ float g_att[MTOK*HID];     // also reused as patch-embed GEMM output
__device__ float g_m1 [MTOK*INTER];
__device__ float g_xp [MPATCH*HID];
__device__ float g_wp [HID*HID];      // transposed conv_w

// ---------------- small kernels ----------------
__global__ void transpose_w(const float* __restrict__ conv_w, float* __restrict__ wp) {
    int idx = blockIdx.x * blockDim.x + threadIdx.x;   // over 768*768
    if (idx >= HID*HID) return;
    int kk = idx / HID, d = idx % HID;
    wp[kk*HID + d] = conv_w[d*HID + kk];
}

__global__ void patchify(const float* __restrict__ x, float* __restrict__ xp) {
    int idx = blockIdx.x * blockDim.x + threadIdx.x;   // over 6272*768
    if (idx >= MPATCH*HID) return;
    int m  = idx / HID;
    int kk = idx % HID;
    int b = m / (GP*GP), r = m % (GP*GP);
    int i = r / GP, j = r % GP;
    int c = kk / (PSZ*PSZ), rem = kk % (PSZ*PSZ);
    int p = rem / PSZ, q = rem % PSZ;
    xp[idx] = x[ ((size_t)(b*3 + c)*IMG + (i*PSZ + p))*IMG + (j*PSZ + q) ];
}

__global__ void build_h(const float* __restrict__ xe, const float* __restrict__ cls,
                        const float* __restrict__ pos, float* __restrict__ h) {
    int idx = blockIdx.x * blockDim.x + threadIdx.x;   // over 6304*768
    if (idx >= MTOK*HID) return;
    int m = idx / HID, d = idx % HID;
    int b = m / SEQ, s = m % SEQ;
    float pv = pos[s*HID + d];
    float v;
    if (s == 0) v = cls[d] + pv;
    else        v = xe[(size_t)(b*(GP*GP) + (s-1))*HID + d] + pv;
    h[idx] = v;
}

__global__ void layernorm_k(const float* __restrict__ x, const float* __restrict__ scale,
                            const float* __restrict__ bias, float* __restrict__ out) {
    int m = blockIdx.x;
    int tid = threadIdx.x;                 // 256 threads, 768 elems
    const float* row = x + (size_t)m*HID;
    float v0 = row[tid], v1 = row[tid+256], v2 = row[tid+512];
    __shared__ float red[256];
    red[tid] = v0 + v1 + v2;
    __syncthreads();
    #pragma unroll
    for (int o = 128; o > 0; o >>= 1) { if (tid < o) red[tid] += red[tid+o]; __syncthreads(); }
    float mu = red[0] * (1.0f/768.0f);
    __syncthreads();
    float d0 = v0-mu, d1 = v1-mu, d2 = v2-mu;
    red[tid] = d0*d0 + d1*d1 + d2*d2;
    __syncthreads();
    #pragma unroll
    for (int o = 128; o > 0; o >>= 1) { if (tid < o) red[tid] += red[tid+o]; __syncthreads(); }
    float rstd = rsqrtf(red[0] * (1.0f/768.0f) + 1e-5f);
    float* orow = out + (size_t)m*HID;
    orow[tid]     = d0*rstd*scale[tid]     + bias[tid];
    orow[tid+256] = d1*rstd*scale[tid+256] + bias[tid+256];
    orow[tid+512] = d2*rstd*scale[tid+512] + bias[tid+512];
}

// ---------------- SGEMM: C[M,N] = A[M,K] @ B + bias (+resid)(+gelu) ----------------
// B addressing: hstride==0 : row-major [K,N] with leading dim ldb
//               hstride>0  : head-blocked [h][k][64]: elem(k,n) at (n>>6)*hstride + k*64 + (n&63)
__global__ __launch_bounds__(256) void sgemm_k(
    const float* __restrict__ A, const float* __restrict__ B, float* __restrict__ C,
    int M, int N, int K, int ldb, int hstride,
    const float* __restrict__ bias, const float* __restrict__ resid, int act)
{
    __shared__ float As[8][128];
    __shared__ float Bs[8][128];
    const int tid = threadIdx.x;
    const int m0 = blockIdx.y * 128;
    const int n0 = blockIdx.x * 128;
    const int tx = tid & 15;
    const int ty = tid >> 4;
    const int arow = tid >> 1;
    const int acol = (tid & 1) << 2;
    const int brow = tid >> 5;
    const int bcol = (tid & 31) << 2;

    float acc[8][8];
    #pragma unroll
    for (int i = 0; i < 8; i++)
        #pragma unroll
        for (int j = 0; j < 8; j++) acc[i][j] = 0.0f;

    const int gm_a = m0 + arow;
    const bool a_ok = (gm_a < M);

    for (int k0 = 0; k0 < K; k0 += 8) {
        float4 av = make_float4(0.f, 0.f, 0.f, 0.f);
        if (a_ok) av = *reinterpret_cast<const float4*>(A + (size_t)gm_a*K + k0 + acol);
        As[acol+0][arow] = av.x; As[acol+1][arow] = av.y;
        As[acol+2][arow] = av.z; As[acol+3][arow] = av.w;

        if (hstride) {
            const int kk = k0 + brow;
            #pragma unroll
            for (int j = 0; j < 4; j++) {
                int n = n0 + bcol + j;
                Bs[brow][bcol+j] = B[(size_t)(n >> 6)*hstride + kk*64 + (n & 63)];
            }
        } else {
            *reinterpret_cast<float4*>(&Bs[brow][bcol]) =
                *reinterpret_cast<const float4*>(B + (size_t)(k0+brow)*ldb + n0 + bcol);
        }
        __syncthreads();

        #pragma unroll
        for (int k = 0; k < 8; k++) {
            float4 a0 = *reinterpret_cast<const float4*>(&As[k][ty*8]);
            float4 a1 = *reinterpret_cast<const float4*>(&As[k][ty*8+4]);
            float4 b0 = *reinterpret_cast<const float4*>(&Bs[k][tx*8]);
            float4 b1 = *reinterpret_cast<const float4*>(&Bs[k][tx*8+4]);
            float aa[8] = {a0.x,a0.y,a0.z,a0.w,a1.x,a1.y,a1.z,a1.w};
            float bb[8] = {b0.x,b0.y,b0.z,b0.w,b1.x,b1.y,b1.z,b1.w};
            #pragma unroll
            for (int i = 0; i < 8; i++)
                #pragma unroll
                for (int j = 0; j < 8; j++) acc[i][j] += aa[i]*bb[j];
        }
        __syncthreads();
    }

    #pragma unroll
    for (int i = 0; i < 8; i++) {
        int gm = m0 + ty*8 + i;
        if (gm >= M) continue;
        #pragma unroll
        for (int j = 0; j < 8; j++) {
            int gn = n0 + tx*8 + j;
            float v = acc[i][j] + bias[gn];
            if (resid) v += resid[(size_t)gm*N + gn];
            if (act)   v = 0.5f*v*(1.0f + erff(v*0.70710678118654752f));
            C[(size_t)gm*N + gn] = v;
        }
    }
}

// ---------------- attention: one block per (b, h) ----------------
// smem: Kh[197*65], Vh[197*65], srow[8*200], qrow[8*64]
#define ATT_SMEM_FLOATS (197*65*2 + 8*200 + 8*64)
__global__ __launch_bounds__(256) void attention_k(
    const float* __restrict__ q, const float* __restrict__ k,
    const float* __restrict__ v, float* __restrict__ att)
{
    extern __shared__ float sm[];
    float* Kh   = sm;
    float* Vh   = sm + 197*65;
    float* srow = Vh + 197*65;
    float* qrow = srow + 8*200;

    int bh = blockIdx.x;
    int b = bh / NH, h = bh % NH;
    int tid = threadIdx.x, wid = tid >> 5, lane = tid & 31;

    const float* kbase = k + (size_t)(b*SEQ)*HID + h*DH;
    const float* vbase = v + (size_t)(b*SEQ)*HID + h*DH;
    for (int idx = tid; idx < SEQ*DH; idx += 256) {
        int t = idx >> 6, dk = idx & 63;
        Kh[t*65 + dk] = kbase[(size_t)t*HID + dk];
        Vh[t*65 + dk] = vbase[(size_t)t*HID + dk];
    }
    __syncthreads();

    const float* qbase = q + (size_t)(b*SEQ)*HID + h*DH;
    float* obase = att + (size_t)(b*SEQ)*HID + h*DH;
    float* myS = srow + wid*200;
    float* myQ = qrow + wid*64;

    for (int s = wid; s < SEQ; s += 8) {
        myQ[lane]      = qbase[(size_t)s*HID + lane];
        myQ[lane + 32] = qbase[(size_t)s*HID + lane + 32];
        __syncwarp();

        float sc[7];
        float mx = -1e30f;
        #pragma unroll
        for (int i = 0; i < 7; i++) {
            int t = lane + 32*i;
            float d = -1e30f;
            if (t < SEQ) {
                d = 0.0f;
                #pragma unroll
                for (int dk = 0; dk < 64; dk++) d += myQ[dk] * Kh[t*65 + dk];
                d *= 0.125f;
            }
            sc[i] = d;
            mx = fmaxf(mx, d);
        }
        #pragma unroll
        for (int o = 16; o > 0; o >>= 1) mx = fmaxf(mx, __shfl_xor_sync(0xffffffffu, mx, o));

        float sum = 0.0f;
        #pragma unroll
        for (int i = 0; i < 7; i++) {
            int t = lane + 32*i;
            float e = (t < SEQ) ? expf(sc[i] - mx) : 0.0f;
            sc[i] = e; sum += e;
        }
        #pragma unroll
        for (int o = 16; o > 0; o >>= 1) sum += __shfl_xor_sync(0xffffffffu, sum, o);
        float inv = 1.0f / sum;

        #pragma unroll
        for (int i = 0; i < 7; i++) {
            int t = lane + 32*i;
            if (t < SEQ) myS[t] = sc[i]*inv;
        }
        __syncwarp();

        float a0 = 0.0f, a1 = 0.0f;
        for (int t = 0; t < SEQ; t++) {
            float p = myS[t];
            a0 += p * Vh[t*65 + lane];
            a1 += p * Vh[t*65 + lane + 32];
        }
        obase[(size_t)s*HID + lane]      = a0;
        obase[(size_t)s*HID + lane + 32] = a1;
        __syncwarp();
    }
}

// ---------------- classifier head ----------------
__global__ void head_k(const float* __restrict__ h, const float* __restrict__ W,
                       const float* __restrict__ bias, float* __restrict__ out) {
    __shared__ float row[HID];
    int b = blockIdx.y;
    int n = blockIdx.x*256 + threadIdx.x;
    const float* hr = h + (size_t)(b*SEQ)*HID;
    for (int i = threadIdx.x; i < HID; i += 256) row[i] = hr[i];
    __syncthreads();
    if (n < NCLS) {
        float acc = bias[n];
        for (int d = 0; d < HID; d++) acc += row[d] * W[(size_t)d*NCLS + n];
        out[(size_t)b*NCLS + n] = acc;
    }
}

// ---------------- host orchestration ----------------
static float* sym_addr(const void* sym) {
    void* p = nullptr;
    cudaGetSymbolAddress(&p, sym);
    return (float*)p;
}

extern "C" void kernel_launch(void* const* d_in, const int* in_sizes, int n_in,
                              void* d_out, int out_size) {
    const float* x      = (const float*)d_in[0];
    const float* conv_w = (const float*)d_in[1];
    const float* conv_b = (const float*)d_in[2];
    const float* cls    = (const float*)d_in[3];
    const float* pos    = (const float*)d_in[4];
    const float* ln1_s  = (const float*)d_in[5];
    const float* ln1_b  = (const float*)d_in[6];
    const float* wq     = (const float*)d_in[7];
    const float* bq     = (const float*)d_in[8];
    const float* wk     = (const float*)d_in[9];
    const float* bk     = (const float*)d_in[10];
    const float* wv     = (const float*)d_in[11];
    const float* bv     = (const float*)d_in[12];
    const float* wo     = (const float*)d_in[13];
    const float* bo     = (const float*)d_in[14];
    const float* ln2_s  = (const float*)d_in[15];
    const float* ln2_b  = (const float*)d_in[16];
    const float* w1     = (const float*)d_in[17];
    const float* b1     = (const float*)d_in[18];
    const float* w2     = (const float*)d_in[19];
    const float* b2     = (const float*)d_in[20];
    const float* head_w = (const float*)d_in[21];
    const float* head_b = (const float*)d_in[22];
    float* out = (float*)d_out;

    float* h_   = sym_addr(g_h);
    float* hn_  = sym_addr(g_hn);
    float* q_   = sym_addr(g_q);
    float* k_   = sym_addr(g_k);
    float* v_   = sym_addr(g_v);
    float* att_ = sym_addr(g_att);
    float* m1_  = sym_addr(g_m1);
    float* xp_  = sym_addr(g_xp);
    float* wp_  = sym_addr(g_wp);

    const int ATT_SMEM = ATT_SMEM_FLOATS * (int)sizeof(float);
    cudaFuncSetAttribute(attention_k, cudaFuncAttributeMaxDynamicSharedMemorySize, ATT_SMEM);

    // ---- patch embedding ----
    transpose_w<<<(HID*HID + 255)/256, 256>>>(conv_w, wp_);
    patchify<<<(MPATCH*HID + 255)/256, 256>>>(x, xp_);
    {   // xe = xp @ wp + conv_b   (xe stored into g_att scratch)
        dim3 grid(HID/128, (MPATCH + 127)/128);
        sgemm_k<<<grid, 256>>>(xp_, wp_, att_, MPATCH, HID, HID, HID, 0, conv_b, nullptr, 0);
    }
    build_h<<<(MTOK*HID + 255)/256, 256>>>(att_, cls, pos, h_);

    const int WSTRIDE  = NH*HID*DH;   // per-layer qkv weight stride (589824)
    const int HSTRIDE  = HID*DH;      // per-head block stride (49152)

    for (int l = 0; l < NLAYER; l++) {
        // --- attention block ---
        layernorm_k<<<MTOK, 256>>>(h_, ln1_s + l*HID, ln1_b + l*HID, hn_);
        {
            dim3 grid(HID/128, (MTOK + 127)/128);
            sgemm_k<<<grid, 256>>>(hn_, wq + (size_t)l*WSTRIDE, q_, MTOK, HID, HID, 0, HSTRIDE, bq + l*HID, nullptr, 0);
            sgemm_k<<<grid, 256>>>(hn_, wk + (size_t)l*WSTRIDE, k_, MTOK, HID, HID, 0, HSTRIDE, bk + l*HID, nullptr, 0);
            sgemm_k<<<grid, 256>>>(hn_, wv + (size_t)l*WSTRIDE, v_, MTOK, HID, HID, 0, HSTRIDE, bv + l*HID, nullptr, 0);
        }
        attention_k<<<BATCH*NH, 256, ATT_SMEM>>>(q_, k_, v_, att_);
        {
            dim3 grid(HID/128, (MTOK + 127)/128);
            sgemm_k<<<grid, 256>>>(att_, wo + (size_t)l*HID*HID, h_, MTOK, HID, HID, HID, 0, bo + l*HID, h_, 0);
        }
        // --- MLP block ---
        layernorm_k<<<MTOK, 256>>>(h_, ln2_s + l*HID, ln2_b + l*HID, hn_);
        {
            dim3 grid(INTER/128, (MTOK + 127)/128);
            sgemm_k<<<grid, 256>>>(hn_, w1 + (size_t)l*HID*INTER, m1_, MTOK, INTER, HID, INTER, 0, b1 + l*INTER, nullptr, 1);
        }
        {
            dim3 grid(HID/128, (MTOK + 127)/128);
            sgemm_k<<<grid, 256>>>(m1_, w2 + (size_t)l*INTER*HID, h_, MTOK, HID, INTER, HID, 0, b2 + l*HID, h_, 0);
        }
    }

    // ---- classifier head ----
    {
        dim3 grid((NCLS + 255)/256, BATCH);
        head_k<<<grid, 256>>>(h_, head_w, head_b, out);
    }
}

// round 5
// speedup vs baseline: 2.1414x; 2.1414x over previous
#include <cuda_runtime.h>
#include <cuda_bf16.h>
#include <math.h>
#include <stdint.h>

#define BATCH 32
#define SEQ   197
#define MTOK  (BATCH*SEQ)
#define HID   768
#define NH    12
#define DH    64
#define INTER 3072
#define NLAYER 12
#define NCLS  1000
#define GP    14
#define PSZ   16
#define IMG   224
#define MPATCH (BATCH*GP*GP)
#define QKVW  2304
typedef __nv_bfloat16 bf16;

__device__ float g_h  [MTOK*HID];
__device__ float g_qkv[MTOK*QKVW];
__device__ bf16 g_hn_h[MTOK*HID];
__device__ bf16 g_hn_l[MTOK*HID];
__device__ bf16 g_at_h[MTOK*HID];
__device__ bf16 g_at_l[MTOK*HID];
__device__ bf16 g_m1_h[MTOK*INTER];
__device__ bf16 g_m1_l[MTOK*INTER];
__device__ bf16 g_xp_h[MPATCH*HID];
__device__ bf16 g_xp_l[MPATCH*HID];
__device__ bf16 g_Wq_h[NLAYER*QKVW*HID];
__device__ bf16 g_Wq_l[NLAYER*QKVW*HID];
__device__ bf16 g_Wo_h[NLAYER*HID*HID];
__device__ bf16 g_Wo_l[NLAYER*HID*HID];
__device__ bf16 g_W1_h[NLAYER*INTER*HID];
__device__ bf16 g_W1_l[NLAYER*INTER*HID];
__device__ bf16 g_W2_h[NLAYER*HID*INTER];
__device__ bf16 g_W2_l[NLAYER*HID*INTER];
__device__ bf16 g_Wp_h[HID*HID];
__device__ bf16 g_Wp_l[HID*HID];
__device__ float g_bq[NLAYER*QKVW];

__device__ __forceinline__ uint32_t smem_u32(const void* p){
    uint32_t a; asm("{ .reg .u64 t; cvta.to.shared.u64 t, %1; cvt.u32.u64 %0, t; }":"=r"(a):"l"(p)); return a;
}

#define LDM4(r, ad) asm volatile("ldmatrix.sync.aligned.m8n8.x4.shared.b16 {%0,%1,%2,%3}, [%4];" \
  : "=r"((r)[0]),"=r"((r)[1]),"=r"((r)[2]),"=r"((r)[3]) : "r"(ad))
#define MMA(d, a, b0, b1) asm volatile( \
  "mma.sync.aligned.m16n8k16.row.col.f32.bf16.bf16.f32 {%0,%1,%2,%3}, {%4,%5,%6,%7}, {%8,%9}, {%0,%1,%2,%3};" \
  : "+f"((d)[0]), "+f"((d)[1]), "+f"((d)[2]), "+f"((d)[3]) \
  : "r"((a)[0]), "r"((a)[1]), "r"((a)[2]), "r"((a)[3]), "r"(b0), "r"(b1))
__device__ __forceinline__ void cpa16(uint32_t dst, const void* src, bool pred){
    asm volatile("cp.async.cg.shared.global [%0], [%1], 16, %2;" :: "r"(dst), "l"(src), "r"(pred?16:0));
}
#define CPA_COMMIT() asm volatile("cp.async.commit_group;" ::: "memory")
#define CPA_WAIT1()  asm volatile("cp.async.wait_group 1;" ::: "memory")
#define CPA_WAIT0()  asm volatile("cp.async.wait_group 0;" ::: "memory")

// ---- bf16-split GEMM via mma.sync: C[M,N] = A[M,K] @ Bt[N,K]^T (3 MMAs/elem) ----
#define BM 128
#define BN 128
#define BK 32
#define SSTR 32768          // per-stage: Ah 8K | Al 8K | Bh 8K | Bl 8K
#define GSMEM 98304         // 3 stages; epilogue reuses 67.6KB of it

__global__ __launch_bounds__(256,1) void tc_gemm(
    const bf16* __restrict__ Ah, const bf16* __restrict__ Al,
    const bf16* __restrict__ Bh, const bf16* __restrict__ Bl,
    int M, int N, int K, const float* __restrict__ bias, const float* __restrict__ resid,
    float* __restrict__ Cf, bf16* __restrict__ Chi, bf16* __restrict__ Clo, int act)
{
    extern __shared__ char smc[];
    const uint32_t sb = smem_u32(smc);
    const int tid = threadIdx.x, wid = tid>>5, lane = tid&31;
    const int m0 = blockIdx.y*BM, n0 = blockIdx.x*BN;
    const int warp_m = wid & 3, warp_n = wid >> 2;

    // loader: 256 threads cover 64 rows x 4 chunks per pass; 2 passes (rows +0, +64)
    const int lr0 = tid >> 2, lc = tid & 3;
    const int lr1 = lr0 + 64;
    const uint32_t sw0 = (uint32_t)(lr0*64 + ((lc ^ ((lr0>>1)&3))<<4));
    const uint32_t sw1 = (uint32_t)(lr1*64 + ((lc ^ ((lr1>>1)&3))<<4));
    const bool a_ok0 = (m0 + lr0) < M;
    const bool a_ok1 = (m0 + lr1) < M;
    const size_t a_g0 = (size_t)(m0 + lr0)*K + lc*8;
    const size_t a_g1 = (size_t)(m0 + lr1)*K + lc*8;
    const size_t b_g0 = (size_t)(n0 + lr0)*K + lc*8;
    const size_t b_g1 = (size_t)(n0 + lr1)*K + lc*8;

    const int nc = K / BK;
    // prologue: stages 0,1
    #pragma unroll
    for (int s = 0; s < 2; s++) {
        const int k0 = s*BK;
        uint32_t d = sb + s*SSTR;
        cpa16(d + sw0,         Ah + a_g0 + k0, a_ok0);
        cpa16(d + sw1,         Ah + a_g1 + k0, a_ok1);
        cpa16(d + 8192 + sw0,  Al + a_g0 + k0, a_ok0);
        cpa16(d + 8192 + sw1,  Al + a_g1 + k0, a_ok1);
        cpa16(d + 16384 + sw0, Bh + b_g0 + k0, true);
        cpa16(d + 16384 + sw1, Bh + b_g1 + k0, true);
        cpa16(d + 24576 + sw0, Bl + b_g0 + k0, true);
        cpa16(d + 24576 + sw1, Bl + b_g1 + k0, true);
        CPA_COMMIT();
    }

    float acc[2][8][4];
    #pragma unroll
    for (int i=0;i<2;i++)
        #pragma unroll
        for (int j=0;j<8;j++)
            #pragma unroll
            for (int t=0;t<4;t++) acc[i][j][t]=0.f;

    const int lrow8 = (lane&7) + ((lane>>3)&1)*8;
    const int lhalf = lane>>4;

    for (int c = 0; c < nc; c++) {
        const int sidx = c % 3;
        CPA_WAIT1();
        __syncthreads();
        if (c + 2 < nc) {
            const int s = (c+2) % 3;
            const int k0 = (c+2)*BK;
            uint32_t d = sb + s*SSTR;
            cpa16(d + sw0,         Ah + a_g0 + k0, a_ok0);
            cpa16(d + sw1,         Ah + a_g1 + k0, a_ok1);
            cpa16(d + 8192 + sw0,  Al + a_g0 + k0, a_ok0);
            cpa16(d + 8192 + sw1,  Al + a_g1 + k0, a_ok1);
            cpa16(d + 16384 + sw0, Bh + b_g0 + k0, true);
            cpa16(d + 16384 + sw1, Bh + b_g1 + k0, true);
            cpa16(d + 24576 + sw0, Bl + b_g0 + k0, true);
            cpa16(d + 24576 + sw1, Bl + b_g1 + k0, true);
            CPA_COMMIT();
        }
        const uint32_t sa = sb + sidx*SSTR;
        #pragma unroll
        for (int kk = 0; kk < 2; kk++) {
            const int c16 = kk*2 + lhalf;
            uint32_t ah[2][4], al[2][4];
            #pragma unroll
            for (int mt = 0; mt < 2; mt++) {
                int row = warp_m*32 + mt*16 + lrow8;
                uint32_t ad = sa + (uint32_t)(row*64 + ((c16 ^ ((row>>1)&3))<<4));
                LDM4(ah[mt], ad);
                LDM4(al[mt], ad + 8192);
            }
            uint32_t bh[4][4], bl[4][4];
            #pragma unroll
            for (int n4 = 0; n4 < 4; n4++) {
                int row = warp_n*64 + n4*16 + lrow8;
                uint32_t bd = sa + 16384 + (uint32_t)(row*64 + ((c16 ^ ((row>>1)&3))<<4));
                LDM4(bh[n4], bd);
                LDM4(bl[n4], bd + 8192);
            }
            #pragma unroll
            for (int mt = 0; mt < 2; mt++)
                #pragma unroll
                for (int nt = 0; nt < 8; nt++) {
                    const int n4 = nt>>1, od = nt&1;
                    MMA(acc[mt][nt], ah[mt], bh[n4][od], bh[n4][od+2]);
                    MMA(acc[mt][nt], ah[mt], bl[n4][od], bl[n4][od+2]);
                    MMA(acc[mt][nt], al[mt], bh[n4][od], bh[n4][od+2]);
                }
        }
    }
    CPA_WAIT0();
    __syncthreads();

    // epilogue: acc -> smem (stride 132) -> coalesced global
    float* stg = (float*)smc;
    const int ST = 132;
    #pragma unroll
    for (int mt = 0; mt < 2; mt++)
        #pragma unroll
        for (int nt = 0; nt < 8; nt++)
            #pragma unroll
            for (int i = 0; i < 4; i++) {
                int row = warp_m*32 + mt*16 + (lane>>2) + (i>>1)*8;
                int col = warp_n*64 + nt*8 + 2*(lane&3) + (i&1);
                stg[row*ST + col] = acc[mt][nt][i];
            }
    __syncthreads();

    #pragma unroll
    for (int i = 0; i < 16; i++) {
        int g = tid + i*256;            // 128 rows x 32 quads
        int r = g >> 5, q = g & 31;
        int gm = m0 + r;
        if (gm >= M) continue;
        int n = n0 + q*4;
        float v0 = stg[r*ST + q*4 + 0] + bias[n+0];
        float v1 = stg[r*ST + q*4 + 1] + bias[n+1];
        float v2 = stg[r*ST + q*4 + 2] + bias[n+2];
        float v3 = stg[r*ST + q*4 + 3] + bias[n+3];
        if (act) {
            v0 = 0.5f*v0*(1.0f+erff(v0*0.70710678118654752f));
            v1 = 0.5f*v1*(1.0f+erff(v1*0.70710678118654752f));
            v2 = 0.5f*v2*(1.0f+erff(v2*0.70710678118654752f));
            v3 = 0.5f*v3*(1.0f+erff(v3*0.70710678118654752f));
        }
        if (resid) {
            const float* rp = resid + (size_t)gm*N + n;
            v0 += rp[0]; v1 += rp[1]; v2 += rp[2]; v3 += rp[3];
        }
        if (Cf) {
            *(float4*)(Cf + (size_t)gm*N + n) = make_float4(v0,v1,v2,v3);
        } else {
            bf16 h0=__float2bfloat16(v0),h1=__float2bfloat16(v1),h2=__float2bfloat16(v2),h3=__float2bfloat16(v3);
            bf16 l0=__float2bfloat16(v0-__bfloat162float(h0)),l1=__float2bfloat16(v1-__bfloat162float(h1));
            bf16 l2=__float2bfloat16(v2-__bfloat162float(h2)),l3=__float2bfloat16(v3-__bfloat162float(h3));
            uint2 sh,sl;
            sh.x=(uint32_t)__bfloat16_as_ushort(h0)|((uint32_t)__bfloat16_as_ushort(h1)<<16);
            sh.y=(uint32_t)__bfloat16_as_ushort(h2)|((uint32_t)__bfloat16_as_ushort(h3)<<16);
            sl.x=(uint32_t)__bfloat16_as_ushort(l0)|((uint32_t)__bfloat16_as_ushort(l1)<<16);
            sl.y=(uint32_t)__bfloat16_as_ushort(l2)|((uint32_t)__bfloat16_as_ushort(l3)<<16);
            *(uint2*)(Chi+(size_t)gm*N+n)=sh; *(uint2*)(Clo+(size_t)gm*N+n)=sl;
        }
    }
}

// ---- weight conversions ----
__global__ void convT_k(const float* __restrict__ in, bf16* __restrict__ hi, bf16* __restrict__ lo, int K, int N){
    __shared__ float t[32][33];
    int l=blockIdx.z; in+=(size_t)l*K*N; hi+=(size_t)l*N*K; lo+=(size_t)l*N*K;
    int n0=blockIdx.x*32, k0=blockIdx.y*32, tx=threadIdx.x, ty=threadIdx.y;
    #pragma unroll
    for (int i=0;i<32;i+=8) t[ty+i][tx]=in[(size_t)(k0+ty+i)*N+n0+tx];
    __syncthreads();
    #pragma unroll
    for (int i=0;i<32;i+=8){
        float v=t[tx][ty+i]; bf16 h=__float2bfloat16(v);
        size_t o=(size_t)(n0+ty+i)*K+k0+tx;
        hi[o]=h; lo[o]=__float2bfloat16(v-__bfloat162float(h));
    }
}
__global__ void convQKV_k(const float* __restrict__ wq, const float* __restrict__ wk, const float* __restrict__ wv,
                          bf16* __restrict__ hi, bf16* __restrict__ lo){
    __shared__ float t[32][33];
    int l=blockIdx.z, k0=blockIdx.x*32, n0=blockIdx.y*32;
    int sel=n0/HID, nn=n0%HID, hh=nn/DH, d0=nn%DH;
    const float* w=(sel==0)?wq:(sel==1)?wk:wv;
    const float* base=w+((size_t)l*NH+hh)*HID*DH;
    int tx=threadIdx.x, ty=threadIdx.y;
    #pragma unroll
    for (int i=0;i<32;i+=8) t[ty+i][tx]=base[(size_t)(k0+ty+i)*DH+d0+tx];
    __syncthreads();
    size_t ob=(size_t)l*QKVW+n0;
    #pragma unroll
    for (int i=0;i<32;i+=8){
        float v=t[tx][ty+i]; bf16 h=__float2bfloat16(v);
        size_t o=(ob+ty+i)*HID+k0+tx;
        hi[o]=h; lo[o]=__float2bfloat16(v-__bfloat162float(h));
    }
}
__global__ void convWP_k(const float* __restrict__ w, bf16* __restrict__ hi, bf16* __restrict__ lo){
    int i=blockIdx.x*blockDim.x+threadIdx.x; if (i>=HID*HID) return;
    float v=w[i]; bf16 h=__float2bfloat16(v);
    hi[i]=h; lo[i]=__float2bfloat16(v-__bfloat162float(h));
}
__global__ void cbias_k(const float* __restrict__ bq, const float* __restrict__ bk, const float* __restrict__ bv, float* __restrict__ o){
    int i=blockIdx.x*blockDim.x+threadIdx.x; if (i>=NLAYER*QKVW) return;
    int l=i/QKVW, n=i%QKVW;
    o[i] = (n<HID)? bq[l*HID+n] : (n<2*HID)? bk[l*HID+n-HID] : bv[l*HID+n-2*HID];
}

// ---- elementwise kernels ----
__global__ void patchify(const float* __restrict__ x, bf16* __restrict__ hi, bf16* __restrict__ lo){
    int idx=blockIdx.x*blockDim.x+threadIdx.x; if (idx>=MPATCH*HID) return;
    int m=idx/HID, kk=idx%HID, b=m/(GP*GP), r=m%(GP*GP), i=r/GP, j=r%GP;
    int c=kk/(PSZ*PSZ), rem=kk%(PSZ*PSZ), p=rem/PSZ, q=rem%PSZ;
    float v=x[((size_t)(b*3+c)*IMG+(i*PSZ+p))*IMG+(j*PSZ+q)];
    bf16 h=__float2bfloat16(v);
    hi[idx]=h; lo[idx]=__float2bfloat16(v-__bfloat162float(h));
}
__global__ void build_h(const float* __restrict__ xe, const float* __restrict__ cls,
                        const float* __restrict__ pos, float* __restrict__ h){
    int idx=blockIdx.x*blockDim.x+threadIdx.x; if (idx>=MTOK*HID) return;
    int m=idx/HID, d=idx%HID, b=m/SEQ, s=m%SEQ;
    float pv=pos[s*HID+d];
    h[idx] = (s==0)? cls[d]+pv : xe[(size_t)(b*(GP*GP)+(s-1))*HID+d]+pv;
}
__global__ void layernorm_k(const float* __restrict__ x, const float* __restrict__ sc,
                            const float* __restrict__ bi, bf16* __restrict__ oh, bf16* __restrict__ ol){
    int m=blockIdx.x, tid=threadIdx.x;
    const float* row=x+(size_t)m*HID;
    float v0=row[tid], v1=row[tid+256], v2=row[tid+512];
    __shared__ float red[256];
    red[tid]=v0+v1+v2; __syncthreads();
    #pragma unroll
    for (int o=128;o>0;o>>=1){ if(tid<o) red[tid]+=red[tid+o]; __syncthreads(); }
    float mu=red[0]*(1.0f/768.0f); __syncthreads();
    float d0=v0-mu,d1=v1-mu,d2=v2-mu;
    red[tid]=d0*d0+d1*d1+d2*d2; __syncthreads();
    #pragma unroll
    for (int o=128;o>0;o>>=1){ if(tid<o) red[tid]+=red[tid+o]; __syncthreads(); }
    float rs=rsqrtf(red[0]*(1.0f/768.0f)+1e-5f);
    size_t base=(size_t)m*HID;
    #pragma unroll
    for (int j=0;j<3;j++){
        int col=tid+j*256;
        float dd=(j==0)?d0:(j==1)?d1:d2;
        float v=dd*rs*sc[col]+bi[col];
        bf16 h=__float2bfloat16(v);
        oh[base+col]=h; ol[base+col]=__float2bfloat16(v-__bfloat162float(h));
    }
}

// ---- attention (fp32, fused qkv input, bf16-split output) ----
#define ATT_SMEMF (197*65*2 + 8*200 + 8*64)
__global__ __launch_bounds__(256) void attention_k(const float* __restrict__ qkv, bf16* __restrict__ oh, bf16* __restrict__ ol){
    extern __shared__ float s[];
    float* Kh=s; float* Vh=s+197*65; float* sr=Vh+197*65; float* qr=sr+8*200;
    int bh=blockIdx.x, b=bh/NH, h=bh%NH;
    int tid=threadIdx.x, wid=tid>>5, lane=tid&31;
    const float* kb=qkv+(size_t)(b*SEQ)*QKVW+HID+h*DH;
    const float* vb=qkv+(size_t)(b*SEQ)*QKVW+2*HID+h*DH;
    for (int idx=tid; idx<SEQ*DH; idx+=256){
        int t=idx>>6, dk=idx&63;
        Kh[t*65+dk]=kb[(size_t)t*QKVW+dk];
        Vh[t*65+dk]=vb[(size_t)t*QKVW+dk];
    }
    __syncthreads();
    const float* qb=qkv+(size_t)(b*SEQ)*QKVW+h*DH;
    size_t ob=(size_t)(b*SEQ)*HID+h*DH;
    float* myS=sr+wid*200; float* myQ=qr+wid*64;
    for (int sq=wid; sq<SEQ; sq+=8){
        myQ[lane]=qb[(size_t)sq*QKVW+lane];
        myQ[lane+32]=qb[(size_t)sq*QKVW+lane+32];
        __syncwarp();
        float scs[7], mx=-1e30f;
        #pragma unroll
        for (int i=0;i<7;i++){
            int t=lane+32*i; float d=-1e30f;
            if (t<SEQ){ d=0.f;
                #pragma unroll
                for (int dk=0;dk<64;dk++) d+=myQ[dk]*Kh[t*65+dk];
                d*=0.125f; }
            scs[i]=d; mx=fmaxf(mx,d);
        }
        #pragma unroll
        for (int o=16;o>0;o>>=1) mx=fmaxf(mx,__shfl_xor_sync(0xffffffffu,mx,o));
        float sum=0.f;
        #pragma unroll
        for (int i=0;i<7;i++){ int t=lane+32*i; float e=(t<SEQ)?expf(scs[i]-mx):0.f; scs[i]=e; sum+=e; }
        #pragma unroll
        for (int o=16;o>0;o>>=1) sum+=__shfl_xor_sync(0xffffffffu,sum,o);
        float inv=1.f/sum;
        #pragma unroll
        for (int i=0;i<7;i++){ int t=lane+32*i; if (t<SEQ) myS[t]=scs[i]*inv; }
        __syncwarp();
        float a0=0.f, a1=0.f;
        for (int t=0;t<SEQ;t++){ float p=myS[t]; a0+=p*Vh[t*65+lane]; a1+=p*Vh[t*65+lane+32]; }
        size_t o0=ob+(size_t)sq*HID+lane;
        bf16 h0=__float2bfloat16(a0), h1=__float2bfloat16(a1);
        oh[o0]=h0; oh[o0+32]=h1;
        ol[o0]=__float2bfloat16(a0-__bfloat162float(h0));
        ol[o0+32]=__float2bfloat16(a1-__bfloat162float(h1));
        __syncwarp();
    }
}

__global__ void head_k(const float* __restrict__ h, const float* __restrict__ W,
                       const float* __restrict__ bi, float* __restrict__ out){
    __shared__ float row[HID];
    int b=blockIdx.y, n=blockIdx.x*256+threadIdx.x;
    const float* hr=h+(size_t)(b*SEQ)*HID;
    for (int i=threadIdx.x;i<HID;i+=256) row[i]=hr[i];
    __syncthreads();
    if (n<NCLS){
        float acc=bi[n];
        for (int d=0;d<HID;d++) acc+=row[d]*W[(size_t)d*NCLS+n];
        out[(size_t)b*NCLS+n]=acc;
    }
}

template<typename T> static T* sym(const void* s){ void* p=nullptr; cudaGetSymbolAddress(&p,s); return (T*)p; }

extern "C" void kernel_launch(void* const* d_in, const int* in_sizes, int n_in, void* d_out, int out_size){
    const float *x=(const float*)d_in[0], *conv_w=(const float*)d_in[1], *conv_b=(const float*)d_in[2];
    const float *cls=(const float*)d_in[3], *pos=(const float*)d_in[4];
    const float *ln1_s=(const float*)d_in[5], *ln1_b=(const float*)d_in[6];
    const float *wq=(const float*)d_in[7], *bq=(const float*)d_in[8];
    const float *wk=(const float*)d_in[9], *bk=(const float*)d_in[10];
    const float *wv=(const float*)d_in[11], *bv=(const float*)d_in[12];
    const float *wo=(const float*)d_in[13], *bo=(const float*)d_in[14];
    const float *ln2_s=(const float*)d_in[15], *ln2_b=(const float*)d_in[16];
    const float *w1=(const float*)d_in[17], *b1=(const float*)d_in[18];
    const float *w2=(const float*)d_in[19], *b2=(const float*)d_in[20];
    const float *head_w=(const float*)d_in[21], *head_b=(const float*)d_in[22];
    float* out=(float*)d_out;

    float* h_  = sym<float>(g_h);
    float* qkv_= sym<float>(g_qkv);
    float* bq_ = sym<float>(g_bq);
    bf16 *hnh=sym<bf16>(g_hn_h), *hnl=sym<bf16>(g_hn_l);
    bf16 *ath=sym<bf16>(g_at_h), *atl=sym<bf16>(g_at_l);
    bf16 *m1h=sym<bf16>(g_m1_h), *m1l=sym<bf16>(g_m1_l);
    bf16 *xph=sym<bf16>(g_xp_h), *xpl=sym<bf16>(g_xp_l);
    bf16 *Wqh=sym<bf16>(g_Wq_h), *Wql=sym<bf16>(g_Wq_l);
    bf16 *Woh=sym<bf16>(g_Wo_h), *Wol=sym<bf16>(g_Wo_l);
    bf16 *W1h=sym<bf16>(g_W1_h), *W1l=sym<bf16>(g_W1_l);
    bf16 *W2h=sym<bf16>(g_W2_h), *W2l=sym<bf16>(g_W2_l);
    bf16 *Wph=sym<bf16>(g_Wp_h), *Wpl=sym<bf16>(g_Wp_l);

    cudaFuncSetAttribute(tc_gemm, cudaFuncAttributeMaxDynamicSharedMemorySize, GSMEM);
    cudaFuncSetAttribute(attention_k, cudaFuncAttributeMaxDynamicSharedMemorySize, ATT_SMEMF*(int)sizeof(float));

    // weight conversion
    dim3 tb(32,8);
    convWP_k<<<(HID*HID+255)/256,256>>>(conv_w, Wph, Wpl);
    convQKV_k<<<dim3(24,72,12),tb>>>(wq,wk,wv,Wqh,Wql);
    convT_k<<<dim3(24,24,12),tb>>>(wo, Woh, Wol, HID, HID);
    convT_k<<<dim3(96,24,12),tb>>>(w1, W1h, W1l, HID, INTER);
    convT_k<<<dim3(24,96,12),tb>>>(w2, W2h, W2l, INTER, HID);
    cbias_k<<<(NLAYER*QKVW+255)/256,256>>>(bq,bk,bv,bq_);

    // patch embed
    patchify<<<(MPATCH*HID+255)/256,256>>>(x, xph, xpl);
    tc_gemm<<<dim3(HID/BN,(MPATCH+BM-1)/BM),256,GSMEM>>>(xph,xpl,Wph,Wpl,MPATCH,HID,HID,conv_b,nullptr,qkv_,nullptr,nullptr,0);
    build_h<<<(MTOK*HID+255)/256,256>>>(qkv_, cls, pos, h_);

    const int MT=(MTOK+BM-1)/BM;
    for (int l=0;l<NLAYER;l++){
        layernorm_k<<<MTOK,256>>>(h_, ln1_s+l*HID, ln1_b+l*HID, hnh, hnl);
        tc_gemm<<<dim3(QKVW/BN,MT),256,GSMEM>>>(hnh,hnl,Wqh+(size_t)l*QKVW*HID,Wql+(size_t)l*QKVW*HID,MTOK,QKVW,HID,bq_+l*QKVW,nullptr,qkv_,nullptr,nullptr,0);
        attention_k<<<BATCH*NH,256,ATT_SMEMF*(int)sizeof(float)>>>(qkv_, ath, atl);
        tc_gemm<<<dim3(HID/BN,MT),256,GSMEM>>>(ath,atl,Woh+(size_t)l*HID*HID,Wol+(size_t)l*HID*HID,MTOK,HID,HID,bo+l*HID,h_,h_,nullptr,nullptr,0);
        layernorm_k<<<MTOK,256>>>(h_, ln2_s+l*HID, ln2_b+l*HID, hnh, hnl);
        tc_gemm<<<dim3(INTER/BN,MT),256,GSMEM>>>(hnh,hnl,W1h+(size_t)l*INTER*HID,W1l+(size_t)l*INTER*HID,MTOK,INTER,HID,b1+l*INTER,nullptr,nullptr,m1h,m1l,1);
        tc_gemm<<<dim3(HID/BN,MT),256,GSMEM>>>(m1h,m1l,W2h+(size_t)l*HID*INTER,W2l+(size_t)l*HID*INTER,MTOK,HID,INTER,b2+l*HID,h_,h_,nullptr,nullptr,0);
    }
    head_k<<<dim3((NCLS+255)/256,BATCH),256>>>(h_, head_w, head_b, out);
}

// round 6
// speedup vs baseline: 2.2745x; 1.0622x over previous
#include <cuda_runtime.h>
#include <cuda_bf16.h>
#include <math.h>
#include <stdint.h>

#define BATCH 32
#define SEQ   197
#define MTOK  (BATCH*SEQ)
#define HID   768
#define NH    12
#define DH    64
#define INTER 3072
#define NLAYER 12
#define NCLS  1000
#define GP    14
#define PSZ   16
#define IMG   224
#define MPATCH (BATCH*GP*GP)
#define QKVW  2304
typedef __nv_bfloat16 bf16;

__device__ float g_h  [MTOK*HID];
__device__ float g_qkv[MTOK*QKVW];
__device__ bf16 g_hn_h[MTOK*HID];
__device__ bf16 g_hn_l[MTOK*HID];
__device__ bf16 g_at_h[MTOK*HID];
__device__ bf16 g_at_l[MTOK*HID];
__device__ bf16 g_m1_h[MTOK*INTER];
__device__ bf16 g_m1_l[MTOK*INTER];
__device__ bf16 g_xp_h[MPATCH*HID];
__device__ bf16 g_xp_l[MPATCH*HID];
__device__ bf16 g_Wq_h[NLAYER*QKVW*HID];
__device__ bf16 g_Wq_l[NLAYER*QKVW*HID];
__device__ bf16 g_Wo_h[NLAYER*HID*HID];
__device__ bf16 g_Wo_l[NLAYER*HID*HID];
__device__ bf16 g_W1_h[NLAYER*INTER*HID];
__device__ bf16 g_W1_l[NLAYER*INTER*HID];
__device__ bf16 g_W2_h[NLAYER*HID*INTER];
__device__ bf16 g_W2_l[NLAYER*HID*INTER];
__device__ bf16 g_Wp_h[HID*HID];
__device__ bf16 g_Wp_l[HID*HID];
__device__ float g_bq[NLAYER*QKVW];

__device__ __forceinline__ uint32_t smem_u32(const void* p){
    uint32_t a; asm("{ .reg .u64 t; cvta.to.shared.u64 t, %1; cvt.u32.u64 %0, t; }":"=r"(a):"l"(p)); return a;
}

#define LDM4(r, ad) asm volatile("ldmatrix.sync.aligned.m8n8.x4.shared.b16 {%0,%1,%2,%3}, [%4];" \
  : "=r"((r)[0]),"=r"((r)[1]),"=r"((r)[2]),"=r"((r)[3]) : "r"(ad))
#define MMA(d, a, b0, b1) asm volatile( \
  "mma.sync.aligned.m16n8k16.row.col.f32.bf16.bf16.f32 {%0,%1,%2,%3}, {%4,%5,%6,%7}, {%8,%9}, {%0,%1,%2,%3};" \
  : "+f"((d)[0]), "+f"((d)[1]), "+f"((d)[2]), "+f"((d)[3]) \
  : "r"((a)[0]), "r"((a)[1]), "r"((a)[2]), "r"((a)[3]), "r"(b0), "r"(b1))
__device__ __forceinline__ void cpa16(uint32_t dst, const void* src, bool pred){
    asm volatile("cp.async.cg.shared.global [%0], [%1], 16, %2;" :: "r"(dst), "l"(src), "r"(pred?16:0));
}
#define CPA_COMMIT() asm volatile("cp.async.commit_group;" ::: "memory")
#define CPA_WAIT1()  asm volatile("cp.async.wait_group 1;" ::: "memory")
#define CPA_WAIT0()  asm volatile("cp.async.wait_group 0;" ::: "memory")

// ---- bf16-split GEMM via mma.sync: C[M,N] = A[M,K] @ Bt[N,K]^T (3 MMAs/elem) ----
// 128x128 block tile, 4 warps, warp tile 64x64, BK=32, 3-stage cp.async.
#define BM 128
#define BN 128
#define BK 32
#define SSTR 32768          // per-stage: Ah 8K | Al 8K | Bh 8K | Bl 8K
#define GSMEM 98304         // 3 stages; epilogue reuses 67.6KB
#define NTHR 128

__device__ __forceinline__ void load_stage(
    uint32_t d, const bf16* __restrict__ Ah, const bf16* __restrict__ Al,
    const bf16* __restrict__ Bh, const bf16* __restrict__ Bl,
    int M, int K, int m0, int n0, int k0, int tid)
{
    const int lc = tid & 3;
    #pragma unroll
    for (int p = 0; p < 4; p++) {
        const int lr = (tid >> 2) + p*32;
        const uint32_t sw = (uint32_t)(lr*64 + ((lc ^ ((lr>>1)&3))<<4));
        const bool aok = (m0 + lr) < M;
        const size_t ag = (size_t)(m0 + lr)*K + k0 + lc*8;
        const size_t bg = (size_t)(n0 + lr)*K + k0 + lc*8;
        cpa16(d + sw,         Ah + ag, aok);
        cpa16(d + 8192 + sw,  Al + ag, aok);
        cpa16(d + 16384 + sw, Bh + bg, true);
        cpa16(d + 24576 + sw, Bl + bg, true);
    }
}

__global__ __launch_bounds__(NTHR,2) void tc_gemm(
    const bf16* __restrict__ Ah, const bf16* __restrict__ Al,
    const bf16* __restrict__ Bh, const bf16* __restrict__ Bl,
    int M, int N, int K, const float* __restrict__ bias, const float* __restrict__ resid,
    float* __restrict__ Cf, bf16* __restrict__ Chi, bf16* __restrict__ Clo, int act)
{
    extern __shared__ char smc[];
    const uint32_t sb = smem_u32(smc);
    const int tid = threadIdx.x, wid = tid>>5, lane = tid&31;
    const int m0 = blockIdx.y*BM, n0 = blockIdx.x*BN;
    const int warp_m = wid & 1, warp_n = wid >> 1;

    const int nc = K / BK;
    #pragma unroll
    for (int s = 0; s < 2; s++) {
        load_stage(sb + s*SSTR, Ah, Al, Bh, Bl, M, K, m0, n0, s*BK, tid);
        CPA_COMMIT();
    }

    float acc[4][8][4];
    #pragma unroll
    for (int i=0;i<4;i++)
        #pragma unroll
        for (int j=0;j<8;j++)
            #pragma unroll
            for (int t=0;t<4;t++) acc[i][j][t]=0.f;

    const int lrow8 = (lane&7) + ((lane>>3)&1)*8;
    const int lhalf = lane>>4;

    for (int c = 0; c < nc; c++) {
        const int sidx = c % 3;
        CPA_WAIT1();
        __syncthreads();
        if (c + 2 < nc) {
            load_stage(sb + ((c+2)%3)*SSTR, Ah, Al, Bh, Bl, M, K, m0, n0, (c+2)*BK, tid);
            CPA_COMMIT();
        }
        const uint32_t sa = sb + sidx*SSTR;
        #pragma unroll
        for (int kk = 0; kk < 2; kk++) {
            const int c16 = kk*2 + lhalf;
            uint32_t ah[4][4], al[4][4];
            #pragma unroll
            for (int mt = 0; mt < 4; mt++) {
                int row = warp_m*64 + mt*16 + lrow8;
                uint32_t ad = sa + (uint32_t)(row*64 + ((c16 ^ ((row>>1)&3))<<4));
                LDM4(ah[mt], ad);
                LDM4(al[mt], ad + 8192);
            }
            #pragma unroll
            for (int n4 = 0; n4 < 4; n4++) {
                int row = warp_n*64 + n4*16 + lrow8;
                uint32_t bd = sa + 16384 + (uint32_t)(row*64 + ((c16 ^ ((row>>1)&3))<<4));
                uint32_t bh[4], bl[4];
                LDM4(bh, bd);
                LDM4(bl, bd + 8192);
                #pragma unroll
                for (int mt = 0; mt < 4; mt++)
                    #pragma unroll
                    for (int od = 0; od < 2; od++) {
                        const int nt = n4*2 + od;
                        MMA(acc[mt][nt], ah[mt], bh[od], bh[od+2]);
                        MMA(acc[mt][nt], ah[mt], bl[od], bl[od+2]);
                        MMA(acc[mt][nt], al[mt], bh[od], bh[od+2]);
                    }
            }
        }
    }
    CPA_WAIT0();
    __syncthreads();

    // epilogue: acc -> smem (stride 132) -> coalesced global
    float* stg = (float*)smc;
    const int ST = 132;
    #pragma unroll
    for (int mt = 0; mt < 4; mt++)
        #pragma unroll
        for (int nt = 0; nt < 8; nt++)
            #pragma unroll
            for (int i = 0; i < 4; i++) {
                int row = warp_m*64 + mt*16 + (lane>>2) + (i>>1)*8;
                int col = warp_n*64 + nt*8 + 2*(lane&3) + (i&1);
                stg[row*ST + col] = acc[mt][nt][i];
            }
    __syncthreads();

    #pragma unroll
    for (int i = 0; i < 32; i++) {
        int g = tid + i*NTHR;           // 128 rows x 32 quads
        int r = g >> 5, q = g & 31;
        int gm = m0 + r;
        if (gm >= M) continue;
        int n = n0 + q*4;
        float v0 = stg[r*ST + q*4 + 0] + bias[n+0];
        float v1 = stg[r*ST + q*4 + 1] + bias[n+1];
        float v2 = stg[r*ST + q*4 + 2] + bias[n+2];
        float v3 = stg[r*ST + q*4 + 3] + bias[n+3];
        if (act) {
            v0 = 0.5f*v0*(1.0f+erff(v0*0.70710678118654752f));
            v1 = 0.5f*v1*(1.0f+erff(v1*0.70710678118654752f));
            v2 = 0.5f*v2*(1.0f+erff(v2*0.70710678118654752f));
            v3 = 0.5f*v3*(1.0f+erff(v3*0.70710678118654752f));
        }
        if (resid) {
            const float* rp = resid + (size_t)gm*N + n;
            v0 += rp[0]; v1 += rp[1]; v2 += rp[2]; v3 += rp[3];
        }
        if (Cf) {
            *(float4*)(Cf + (size_t)gm*N + n) = make_float4(v0,v1,v2,v3);
        } else {
            bf16 h0=__float2bfloat16(v0),h1=__float2bfloat16(v1),h2=__float2bfloat16(v2),h3=__float2bfloat16(v3);
            bf16 l0=__float2bfloat16(v0-__bfloat162float(h0)),l1=__float2bfloat16(v1-__bfloat162float(h1));
            bf16 l2=__float2bfloat16(v2-__bfloat162float(h2)),l3=__float2bfloat16(v3-__bfloat162float(h3));
            uint2 sh,sl;
            sh.x=(uint32_t)__bfloat16_as_ushort(h0)|((uint32_t)__bfloat16_as_ushort(h1)<<16);
            sh.y=(uint32_t)__bfloat16_as_ushort(h2)|((uint32_t)__bfloat16_as_ushort(h3)<<16);
            sl.x=(uint32_t)__bfloat16_as_ushort(l0)|((uint32_t)__bfloat16_as_ushort(l1)<<16);
            sl.y=(uint32_t)__bfloat16_as_ushort(l2)|((uint32_t)__bfloat16_as_ushort(l3)<<16);
            *(uint2*)(Chi+(size_t)gm*N+n)=sh; *(uint2*)(Clo+(size_t)gm*N+n)=sl;
        }
    }
}

// ---- weight conversions ----
__global__ void convT_k(const float* __restrict__ in, bf16* __restrict__ hi, bf16* __restrict__ lo, int K, int N){
    __shared__ float t[32][33];
    int l=blockIdx.z; in+=(size_t)l*K*N; hi+=(size_t)l*N*K; lo+=(size_t)l*N*K;
    int n0=blockIdx.x*32, k0=blockIdx.y*32, tx=threadIdx.x, ty=threadIdx.y;
    #pragma unroll
    for (int i=0;i<32;i+=8) t[ty+i][tx]=in[(size_t)(k0+ty+i)*N+n0+tx];
    __syncthreads();
    #pragma unroll
    for (int i=0;i<32;i+=8){
        float v=t[tx][ty+i]; bf16 h=__float2bfloat16(v);
        size_t o=(size_t)(n0+ty+i)*K+k0+tx;
        hi[o]=h; lo[o]=__float2bfloat16(v-__bfloat162float(h));
    }
}
__global__ void convQKV_k(const float* __restrict__ wq, const float* __restrict__ wk, const float* __restrict__ wv,
                          bf16* __restrict__ hi, bf16* __restrict__ lo){
    __shared__ float t[32][33];
    int l=blockIdx.z, k0=blockIdx.x*32, n0=blockIdx.y*32;
    int sel=n0/HID, nn=n0%HID, hh=nn/DH, d0=nn%DH;
    const float* w=(sel==0)?wq:(sel==1)?wk:wv;
    const float* base=w+((size_t)l*NH+hh)*HID*DH;
    int tx=threadIdx.x, ty=threadIdx.y;
    #pragma unroll
    for (int i=0;i<32;i+=8) t[ty+i][tx]=base[(size_t)(k0+ty+i)*DH+d0+tx];
    __syncthreads();
    size_t ob=(size_t)l*QKVW+n0;
    #pragma unroll
    for (int i=0;i<32;i+=8){
        float v=t[tx][ty+i]; bf16 h=__float2bfloat16(v);
        size_t o=(ob+ty+i)*HID+k0+tx;
        hi[o]=h; lo[o]=__float2bfloat16(v-__bfloat162float(h));
    }
}
__global__ void convWP_k(const float* __restrict__ w, bf16* __restrict__ hi, bf16* __restrict__ lo){
    int i=blockIdx.x*blockDim.x+threadIdx.x; if (i>=HID*HID) return;
    float v=w[i]; bf16 h=__float2bfloat16(v);
    hi[i]=h; lo[i]=__float2bfloat16(v-__bfloat162float(h));
}
__global__ void cbias_k(const float* __restrict__ bq, const float* __restrict__ bk, const float* __restrict__ bv, float* __restrict__ o){
    int i=blockIdx.x*blockDim.x+threadIdx.x; if (i>=NLAYER*QKVW) return;
    int l=i/QKVW, n=i%QKVW;
    o[i] = (n<HID)? bq[l*HID+n] : (n<2*HID)? bk[l*HID+n-HID] : bv[l*HID+n-2*HID];
}

// ---- elementwise kernels ----
__global__ void patchify(const float* __restrict__ x, bf16* __restrict__ hi, bf16* __restrict__ lo){
    int idx=blockIdx.x*blockDim.x+threadIdx.x; if (idx>=MPATCH*HID) return;
    int m=idx/HID, kk=idx%HID, b=m/(GP*GP), r=m%(GP*GP), i=r/GP, j=r%GP;
    int c=kk/(PSZ*PSZ), rem=kk%(PSZ*PSZ), p=rem/PSZ, q=rem%PSZ;
    float v=x[((size_t)(b*3+c)*IMG+(i*PSZ+p))*IMG+(j*PSZ+q)];
    bf16 h=__float2bfloat16(v);
    hi[idx]=h; lo[idx]=__float2bfloat16(v-__bfloat162float(h));
}
__global__ void build_h(const float* __restrict__ xe, const float* __restrict__ cls,
                        const float* __restrict__ pos, float* __restrict__ h){
    int idx=blockIdx.x*blockDim.x+threadIdx.x; if (idx>=MTOK*HID) return;
    int m=idx/HID, d=idx%HID, b=m/SEQ, s=m%SEQ;
    float pv=pos[s*HID+d];
    h[idx] = (s==0)? cls[d]+pv : xe[(size_t)(b*(GP*GP)+(s-1))*HID+d]+pv;
}
__global__ void layernorm_k(const float* __restrict__ x, const float* __restrict__ sc,
                            const float* __restrict__ bi, bf16* __restrict__ oh, bf16* __restrict__ ol){
    int m=blockIdx.x, tid=threadIdx.x;
    const float* row=x+(size_t)m*HID;
    float v0=row[tid], v1=row[tid+256], v2=row[tid+512];
    __shared__ float red[256];
    red[tid]=v0+v1+v2; __syncthreads();
    #pragma unroll
    for (int o=128;o>0;o>>=1){ if(tid<o) red[tid]+=red[tid+o]; __syncthreads(); }
    float mu=red[0]*(1.0f/768.0f); __syncthreads();
    float d0=v0-mu,d1=v1-mu,d2=v2-mu;
    red[tid]=d0*d0+d1*d1+d2*d2; __syncthreads();
    #pragma unroll
    for (int o=128;o>0;o>>=1){ if(tid<o) red[tid]+=red[tid+o]; __syncthreads(); }
    float rs=rsqrtf(red[0]*(1.0f/768.0f)+1e-5f);
    size_t base=(size_t)m*HID;
    #pragma unroll
    for (int j=0;j<3;j++){
        int col=tid+j*256;
        float dd=(j==0)?d0:(j==1)?d1:d2;
        float v=dd*rs*sc[col]+bi[col];
        bf16 h=__float2bfloat16(v);
        oh[base+col]=h; ol[base+col]=__float2bfloat16(v-__bfloat162float(h));
    }
}

// ---- attention (fp32, fused qkv input, bf16-split output) ----
#define ATT_SMEMF (197*65*2 + 8*200 + 8*64)
__global__ __launch_bounds__(256) void attention_k(const float* __restrict__ qkv, bf16* __restrict__ oh, bf16* __restrict__ ol){
    extern __shared__ float s[];
    float* Kh=s; float* Vh=s+197*65; float* sr=Vh+197*65; float* qr=sr+8*200;
    int bh=blockIdx.x, b=bh/NH, h=bh%NH;
    int tid=threadIdx.x, wid=tid>>5, lane=tid&31;
    const float* kb=qkv+(size_t)(b*SEQ)*QKVW+HID+h*DH;
    const float* vb=qkv+(size_t)(b*SEQ)*QKVW+2*HID+h*DH;
    for (int idx=tid; idx<SEQ*DH; idx+=256){
        int t=idx>>6, dk=idx&63;
        Kh[t*65+dk]=kb[(size_t)t*QKVW+dk];
        Vh[t*65+dk]=vb[(size_t)t*QKVW+dk];
    }
    __syncthreads();
    const float* qb=qkv+(size_t)(b*SEQ)*QKVW+h*DH;
    size_t ob=(size_t)(b*SEQ)*HID+h*DH;
    float* myS=sr+wid*200; float* myQ=qr+wid*64;
    for (int sq=wid; sq<SEQ; sq+=8){
        myQ[lane]=qb[(size_t)sq*QKVW+lane];
        myQ[lane+32]=qb[(size_t)sq*QKVW+lane+32];
        __syncwarp();
        float scs[7], mx=-1e30f;
        #pragma unroll
        for (int i=0;i<7;i++){
            int t=lane+32*i; float d=-1e30f;
            if (t<SEQ){ d=0.f;
                #pragma unroll
                for (int dk=0;dk<64;dk++) d+=myQ[dk]*Kh[t*65+dk];
                d*=0.125f; }
            scs[i]=d; mx=fmaxf(mx,d);
        }
        #pragma unroll
        for (int o=16;o>0;o>>=1) mx=fmaxf(mx,__shfl_xor_sync(0xffffffffu,mx,o));
        float sum=0.f;
        #pragma unroll
        for (int i=0;i<7;i++){ int t=lane+32*i; float e=(t<SEQ)?expf(scs[i]-mx):0.f; scs[i]=e; sum+=e; }
        #pragma unroll
        for (int o=16;o>0;o>>=1) sum+=__shfl_xor_sync(0xffffffffu,sum,o);
        float inv=1.f/sum;
        #pragma unroll
        for (int i=0;i<7;i++){ int t=lane+32*i; if (t<SEQ) myS[t]=scs[i]*inv; }
        __syncwarp();
        float a0=0.f, a1=0.f;
        for (int t=0;t<SEQ;t++){ float p=myS[t]; a0+=p*Vh[t*65+lane]; a1+=p*Vh[t*65+lane+32]; }
        size_t o0=ob+(size_t)sq*HID+lane;
        bf16 h0=__float2bfloat16(a0), h1=__float2bfloat16(a1);
        oh[o0]=h0; oh[o0+32]=h1;
        ol[o0]=__float2bfloat16(a0-__bfloat162float(h0));
        ol[o0+32]=__float2bfloat16(a1-__bfloat162float(h1));
        __syncwarp();
    }
}

__global__ void head_k(const float* __restrict__ h, const float* __restrict__ W,
                       const float* __restrict__ bi, float* __restrict__ out){
    __shared__ float row[HID];
    int b=blockIdx.y, n=blockIdx.x*256+threadIdx.x;
    const float* hr=h+(size_t)(b*SEQ)*HID;
    for (int i=threadIdx.x;i<HID;i+=256) row[i]=hr[i];
    __syncthreads();
    if (n<NCLS){
        float acc=bi[n];
        for (int d=0;d<HID;d++) acc+=row[d]*W[(size_t)d*NCLS+n];
        out[(size_t)b*NCLS+n]=acc;
    }
}

template<typename T> static T* sym(const void* s){ void* p=nullptr; cudaGetSymbolAddress(&p,s); return (T*)p; }

extern "C" void kernel_launch(void* const* d_in, const int* in_sizes, int n_in, void* d_out, int out_size){
    const float *x=(const float*)d_in[0], *conv_w=(const float*)d_in[1], *conv_b=(const float*)d_in[2];
    const float *cls=(const float*)d_in[3], *pos=(const float*)d_in[4];
    const float *ln1_s=(const float*)d_in[5], *ln1_b=(const float*)d_in[6];
    const float *wq=(const float*)d_in[7], *bq=(const float*)d_in[8];
    const float *wk=(const float*)d_in[9], *bk=(const float*)d_in[10];
    const float *wv=(const float*)d_in[11], *bv=(const float*)d_in[12];
    const float *wo=(const float*)d_in[13], *bo=(const float*)d_in[14];
    const float *ln2_s=(const float*)d_in[15], *ln2_b=(const float*)d_in[16];
    const float *w1=(const float*)d_in[17], *b1=(const float*)d_in[18];
    const float *w2=(const float*)d_in[19], *b2=(const float*)d_in[20];
    const float *head_w=(const float*)d_in[21], *head_b=(const float*)d_in[22];
    float* out=(float*)d_out;

    float* h_  = sym<float>(g_h);
    float* qkv_= sym<float>(g_qkv);
    float* bq_ = sym<float>(g_bq);
    bf16 *hnh=sym<bf16>(g_hn_h), *hnl=sym<bf16>(g_hn_l);
    bf16 *ath=sym<bf16>(g_at_h), *atl=sym<bf16>(g_at_l);
    bf16 *m1h=sym<bf16>(g_m1_h), *m1l=sym<bf16>(g_m1_l);
    bf16 *xph=sym<bf16>(g_xp_h), *xpl=sym<bf16>(g_xp_l);
    bf16 *Wqh=sym<bf16>(g_Wq_h), *Wql=sym<bf16>(g_Wq_l);
    bf16 *Woh=sym<bf16>(g_Wo_h), *Wol=sym<bf16>(g_Wo_l);
    bf16 *W1h=sym<bf16>(g_W1_h), *W1l=sym<bf16>(g_W1_l);
    bf16 *W2h=sym<bf16>(g_W2_h), *W2l=sym<bf16>(g_W2_l);
    bf16 *Wph=sym<bf16>(g_Wp_h), *Wpl=sym<bf16>(g_Wp_l);

    cudaFuncSetAttribute(tc_gemm, cudaFuncAttributeMaxDynamicSharedMemorySize, GSMEM);
    cudaFuncSetAttribute(attention_k, cudaFuncAttributeMaxDynamicSharedMemorySize, ATT_SMEMF*(int)sizeof(float));

    // weight conversion
    dim3 tb(32,8);
    convWP_k<<<(HID*HID+255)/256,256>>>(conv_w, Wph, Wpl);
    convQKV_k<<<dim3(24,72,12),tb>>>(wq,wk,wv,Wqh,Wql);
    convT_k<<<dim3(24,24,12),tb>>>(wo, Woh, Wol, HID, HID);
    convT_k<<<dim3(96,24,12),tb>>>(w1, W1h, W1l, HID, INTER);
    convT_k<<<dim3(24,96,12),tb>>>(w2, W2h, W2l, INTER, HID);
    cbias_k<<<(NLAYER*QKVW+255)/256,256>>>(bq,bk,bv,bq_);

    // patch embed
    patchify<<<(MPATCH*HID+255)/256,256>>>(x, xph, xpl);
    tc_gemm<<<dim3(HID/BN,(MPATCH+BM-1)/BM),NTHR,GSMEM>>>(xph,xpl,Wph,Wpl,MPATCH,HID,HID,conv_b,nullptr,qkv_,nullptr,nullptr,0);
    build_h<<<(MTOK*HID+255)/256,256>>>(qkv_, cls, pos, h_);

    const int MT=(MTOK+BM-1)/BM;
    for (int l=0;l<NLAYER;l++){
        layernorm_k<<<MTOK,256>>>(h_, ln1_s+l*HID, ln1_b+l*HID, hnh, hnl);
        tc_gemm<<<dim3(QKVW/BN,MT),NTHR,GSMEM>>>(hnh,hnl,Wqh+(size_t)l*QKVW*HID,Wql+(size_t)l*QKVW*HID,MTOK,QKVW,HID,bq_+l*QKVW,nullptr,qkv_,nullptr,nullptr,0);
        attention_k<<<BATCH*NH,256,ATT_SMEMF*(int)sizeof(float)>>>(qkv_, ath, atl);
        tc_gemm<<<dim3(HID/BN,MT),NTHR,GSMEM>>>(ath,atl,Woh+(size_t)l*HID*HID,Wol+(size_t)l*HID*HID,MTOK,HID,HID,bo+l*HID,h_,h_,nullptr,nullptr,0);
        layernorm_k<<<MTOK,256>>>(h_, ln2_s+l*HID, ln2_b+l*HID, hnh, hnl);
        tc_gemm<<<dim3(INTER/BN,MT),NTHR,GSMEM>>>(hnh,hnl,W1h+(size_t)l*INTER*HID,W1l+(size_t)l*INTER*HID,MTOK,INTER,HID,b1+l*INTER,nullptr,nullptr,m1h,m1l,1);
        tc_gemm<<<dim3(HID/BN,MT),NTHR,GSMEM>>>(m1h,m1l,W2h+(size_t)l*HID*INTER,W2l+(size_t)l*HID*INTER,MTOK,HID,INTER,b2+l*HID,h_,h_,nullptr,nullptr,0);
    }
    head_k<<<dim3((NCLS+255)/256,BATCH),256>>>(h_, head_w, head_b, out);
}

// round 7
// speedup vs baseline: 2.7743x; 1.2198x over previous
#include <cuda_runtime.h>
#include <cuda_fp16.h>
#include <math.h>
#include <stdint.h>

#define BATCH 32
#define SEQ   197
#define MTOK  (BATCH*SEQ)
#define HID   768
#define NH    12
#define DH    64
#define INTER 3072
#define NLAYER 12
#define NCLS  1000
#define GP    14
#define PSZ   16
#define IMG   224
#define MPATCH (BATCH*GP*GP)
#define QKVW  2304
typedef __half fp16;

__device__ float g_h  [MTOK*HID];
__device__ float g_qkv[MTOK*QKVW];
__device__ fp16 g_hn_h[MTOK*HID];
__device__ fp16 g_hn_l[MTOK*HID];
__device__ fp16 g_at_h[MTOK*HID];
__device__ fp16 g_at_l[MTOK*HID];
__device__ fp16 g_m1_h[MTOK*INTER];
__device__ fp16 g_m1_l[MTOK*INTER];
__device__ fp16 g_xp_h[MPATCH*HID];
__device__ fp16 g_xp_l[MPATCH*HID];
__device__ fp16 g_Wq_h[NLAYER*QKVW*HID];
__device__ fp16 g_Wo_h[NLAYER*HID*HID];
__device__ fp16 g_W1_h[NLAYER*INTER*HID];
__device__ fp16 g_W2_h[NLAYER*HID*INTER];
__device__ fp16 g_Wp_h[HID*HID];
__device__ float g_bq[NLAYER*QKVW];

__device__ __forceinline__ uint32_t smem_u32(const void* p){
    uint32_t a; asm("{ .reg .u64 t; cvta.to.shared.u64 t, %1; cvt.u32.u64 %0, t; }":"=r"(a):"l"(p)); return a;
}

#define LDM4(r, ad) asm volatile("ldmatrix.sync.aligned.m8n8.x4.shared.b16 {%0,%1,%2,%3}, [%4];" \
  : "=r"((r)[0]),"=r"((r)[1]),"=r"((r)[2]),"=r"((r)[3]) : "r"(ad))
#define MMA(d, a, b0, b1) asm volatile( \
  "mma.sync.aligned.m16n8k16.row.col.f32.f16.f16.f32 {%0,%1,%2,%3}, {%4,%5,%6,%7}, {%8,%9}, {%0,%1,%2,%3};" \
  : "+f"((d)[0]), "+f"((d)[1]), "+f"((d)[2]), "+f"((d)[3]) \
  : "r"((a)[0]), "r"((a)[1]), "r"((a)[2]), "r"((a)[3]), "r"(b0), "r"(b1))
__device__ __forceinline__ void cpa16(uint32_t dst, const void* src, bool pred){
    asm volatile("cp.async.cg.shared.global [%0], [%1], 16, %2;" :: "r"(dst), "l"(src), "r"(pred?16:0));
}
#define CPA_COMMIT() asm volatile("cp.async.commit_group;" ::: "memory")
#define CPA_WAIT1()  asm volatile("cp.async.wait_group 1;" ::: "memory")
#define CPA_WAIT0()  asm volatile("cp.async.wait_group 0;" ::: "memory")

// ---- fp16 2-MMA split GEMM: C[M,N] = (Ah+Al)[M,K] @ Bh[N,K]^T, fp32 accum ----
// 128x128 block tile, 4 warps, warp tile 64x64, BK=32, 3-stage cp.async.
#define BM 128
#define BN 128
#define BK 32
#define SSTR 24576          // per-stage: Ah 8K | Al 8K | Bh 8K
#define GSMEM 73728         // 3 stages; epilogue (67.6KB) reuses it
#define NTHR 128

__device__ __forceinline__ void load_stage(
    uint32_t d, const fp16* __restrict__ Ah, const fp16* __restrict__ Al,
    const fp16* __restrict__ Bh,
    int M, int K, int m0, int n0, int k0, int tid)
{
    const int lc = tid & 3;
    #pragma unroll
    for (int p = 0; p < 4; p++) {
        const int lr = (tid >> 2) + p*32;
        const uint32_t sw = (uint32_t)(lr*64 + ((lc ^ ((lr>>1)&3))<<4));
        const bool aok = (m0 + lr) < M;
        const size_t ag = (size_t)(m0 + lr)*K + k0 + lc*8;
        const size_t bg = (size_t)(n0 + lr)*K + k0 + lc*8;
        cpa16(d + sw,         Ah + ag, aok);
        cpa16(d + 8192 + sw,  Al + ag, aok);
        cpa16(d + 16384 + sw, Bh + bg, true);
    }
}

__global__ __launch_bounds__(NTHR,2) void tc_gemm(
    const fp16* __restrict__ Ah, const fp16* __restrict__ Al,
    const fp16* __restrict__ Bh,
    int M, int N, int K, const float* __restrict__ bias, const float* __restrict__ resid,
    float* __restrict__ Cf, fp16* __restrict__ Chi, fp16* __restrict__ Clo, int act)
{
    extern __shared__ char smc[];
    const uint32_t sb = smem_u32(smc);
    const int tid = threadIdx.x, wid = tid>>5, lane = tid&31;
    const int m0 = blockIdx.y*BM, n0 = blockIdx.x*BN;
    const int warp_m = wid & 1, warp_n = wid >> 1;

    const int nc = K / BK;
    #pragma unroll
    for (int s = 0; s < 2; s++) {
        load_stage(sb + s*SSTR, Ah, Al, Bh, M, K, m0, n0, s*BK, tid);
        CPA_COMMIT();
    }

    float acc[4][8][4];
    #pragma unroll
    for (int i=0;i<4;i++)
        #pragma unroll
        for (int j=0;j<8;j++)
            #pragma unroll
            for (int t=0;t<4;t++) acc[i][j][t]=0.f;

    const int lrow8 = (lane&7) + ((lane>>3)&1)*8;
    const int lhalf = lane>>4;

    for (int c = 0; c < nc; c++) {
        const int sidx = c % 3;
        CPA_WAIT1();
        __syncthreads();
        if (c + 2 < nc) {
            load_stage(sb + ((c+2)%3)*SSTR, Ah, Al, Bh, M, K, m0, n0, (c+2)*BK, tid);
            CPA_COMMIT();
        }
        const uint32_t sa = sb + sidx*SSTR;
        #pragma unroll
        for (int kk = 0; kk < 2; kk++) {
            const int c16 = kk*2 + lhalf;
            uint32_t ah[4][4], al[4][4];
            #pragma unroll
            for (int mt = 0; mt < 4; mt++) {
                int row = warp_m*64 + mt*16 + lrow8;
                uint32_t ad = sa + (uint32_t)(row*64 + ((c16 ^ ((row>>1)&3))<<4));
                LDM4(ah[mt], ad);
                LDM4(al[mt], ad + 8192);
            }
            #pragma unroll
            for (int n4 = 0; n4 < 4; n4++) {
                int row = warp_n*64 + n4*16 + lrow8;
                uint32_t bd = sa + 16384 + (uint32_t)(row*64 + ((c16 ^ ((row>>1)&3))<<4));
                uint32_t bh[4];
                LDM4(bh, bd);
                #pragma unroll
                for (int mt = 0; mt < 4; mt++)
                    #pragma unroll
                    for (int od = 0; od < 2; od++) {
                        const int nt = n4*2 + od;
                        MMA(acc[mt][nt], ah[mt], bh[od], bh[od+2]);
                        MMA(acc[mt][nt], al[mt], bh[od], bh[od+2]);
                    }
            }
        }
    }
    CPA_WAIT0();
    __syncthreads();

    // epilogue: acc -> smem (stride 132) -> coalesced global
    float* stg = (float*)smc;
    const int ST = 132;
    #pragma unroll
    for (int mt = 0; mt < 4; mt++)
        #pragma unroll
        for (int nt = 0; nt < 8; nt++)
            #pragma unroll
            for (int i = 0; i < 4; i++) {
                int row = warp_m*64 + mt*16 + (lane>>2) + (i>>1)*8;
                int col = warp_n*64 + nt*8 + 2*(lane&3) + (i&1);
                stg[row*ST + col] = acc[mt][nt][i];
            }
    __syncthreads();

    #pragma unroll
    for (int i = 0; i < 32; i++) {
        int g = tid + i*NTHR;           // 128 rows x 32 quads
        int r = g >> 5, q = g & 31;
        int gm = m0 + r;
        if (gm >= M) continue;
        int n = n0 + q*4;
        float v0 = stg[r*ST + q*4 + 0] + bias[n+0];
        float v1 = stg[r*ST + q*4 + 1] + bias[n+1];
        float v2 = stg[r*ST + q*4 + 2] + bias[n+2];
        float v3 = stg[r*ST + q*4 + 3] + bias[n+3];
        if (act) {
            v0 = 0.5f*v0*(1.0f+erff(v0*0.70710678118654752f));
            v1 = 0.5f*v1*(1.0f+erff(v1*0.70710678118654752f));
            v2 = 0.5f*v2*(1.0f+erff(v2*0.70710678118654752f));
            v3 = 0.5f*v3*(1.0f+erff(v3*0.70710678118654752f));
        }
        if (resid) {
            const float* rp = resid + (size_t)gm*N + n;
            v0 += rp[0]; v1 += rp[1]; v2 += rp[2]; v3 += rp[3];
        }
        if (Cf) {
            *(float4*)(Cf + (size_t)gm*N + n) = make_float4(v0,v1,v2,v3);
        } else {
            fp16 h0=__float2half(v0),h1=__float2half(v1),h2=__float2half(v2),h3=__float2half(v3);
            fp16 l0=__float2half(v0-__half2float(h0)),l1=__float2half(v1-__half2float(h1));
            fp16 l2=__float2half(v2-__half2float(h2)),l3=__float2half(v3-__half2float(h3));
            uint2 sh,sl;
            sh.x=(uint32_t)__half_as_ushort(h0)|((uint32_t)__half_as_ushort(h1)<<16);
            sh.y=(uint32_t)__half_as_ushort(h2)|((uint32_t)__half_as_ushort(h3)<<16);
            sl.x=(uint32_t)__half_as_ushort(l0)|((uint32_t)__half_as_ushort(l1)<<16);
            sl.y=(uint32_t)__half_as_ushort(l2)|((uint32_t)__half_as_ushort(l3)<<16);
            *(uint2*)(Chi+(size_t)gm*N+n)=sh; *(uint2*)(Clo+(size_t)gm*N+n)=sl;
        }
    }
}

// ---- weight conversions (hi fp16 only) ----
__global__ void convT_k(const float* __restrict__ in, fp16* __restrict__ hi, int K, int N){
    __shared__ float t[32][33];
    int l=blockIdx.z; in+=(size_t)l*K*N; hi+=(size_t)l*N*K;
    int n0=blockIdx.x*32, k0=blockIdx.y*32, tx=threadIdx.x, ty=threadIdx.y;
    #pragma unroll
    for (int i=0;i<32;i+=8) t[ty+i][tx]=in[(size_t)(k0+ty+i)*N+n0+tx];
    __syncthreads();
    #pragma unroll
    for (int i=0;i<32;i+=8)
        hi[(size_t)(n0+ty+i)*K+k0+tx]=__float2half(t[tx][ty+i]);
}
__global__ void convQKV_k(const float* __restrict__ wq, const float* __restrict__ wk, const float* __restrict__ wv,
                          fp16* __restrict__ hi){
    __shared__ float t[32][33];
    int l=blockIdx.z, k0=blockIdx.x*32, n0=blockIdx.y*32;
    int sel=n0/HID, nn=n0%HID, hh=nn/DH, d0=nn%DH;
    const float* w=(sel==0)?wq:(sel==1)?wk:wv;
    const float* base=w+((size_t)l*NH+hh)*HID*DH;
    int tx=threadIdx.x, ty=threadIdx.y;
    #pragma unroll
    for (int i=0;i<32;i+=8) t[ty+i][tx]=base[(size_t)(k0+ty+i)*DH+d0+tx];
    __syncthreads();
    size_t ob=(size_t)l*QKVW+n0;
    #pragma unroll
    for (int i=0;i<32;i+=8)
        hi[(ob+ty+i)*HID+k0+tx]=__float2half(t[tx][ty+i]);
}
__global__ void convWP_k(const float* __restrict__ w, fp16* __restrict__ hi){
    int i=blockIdx.x*blockDim.x+threadIdx.x; if (i>=HID*HID) return;
    hi[i]=__float2half(w[i]);
}
__global__ void cbias_k(const float* __restrict__ bq, const float* __restrict__ bk, const float* __restrict__ bv, float* __restrict__ o){
    int i=blockIdx.x*blockDim.x+threadIdx.x; if (i>=NLAYER*QKVW) return;
    int l=i/QKVW, n=i%QKVW;
    o[i] = (n<HID)? bq[l*HID+n] : (n<2*HID)? bk[l*HID+n-HID] : bv[l*HID+n-2*HID];
}

// ---- elementwise kernels ----
__global__ void patchify(const float* __restrict__ x, fp16* __restrict__ hi, fp16* __restrict__ lo){
    int idx=blockIdx.x*blockDim.x+threadIdx.x; if (idx>=MPATCH*HID) return;
    int m=idx/HID, kk=idx%HID, b=m/(GP*GP), r=m%(GP*GP), i=r/GP, j=r%GP;
    int c=kk/(PSZ*PSZ), rem=kk%(PSZ*PSZ), p=rem/PSZ, q=rem%PSZ;
    float v=x[((size_t)(b*3+c)*IMG+(i*PSZ+p))*IMG+(j*PSZ+q)];
    fp16 h=__float2half(v);
    hi[idx]=h; lo[idx]=__float2half(v-__half2float(h));
}
__global__ void build_h(const float* __restrict__ xe, const float* __restrict__ cls,
                        const float* __restrict__ pos, float* __restrict__ h){
    int idx=blockIdx.x*blockDim.x+threadIdx.x; if (idx>=MTOK*HID) return;
    int m=idx/HID, d=idx%HID, b=m/SEQ, s=m%SEQ;
    float pv=pos[s*HID+d];
    h[idx] = (s==0)? cls[d]+pv : xe[(size_t)(b*(GP*GP)+(s-1))*HID+d]+pv;
}
__global__ void layernorm_k(const float* __restrict__ x, const float* __restrict__ sc,
                            const float* __restrict__ bi, fp16* __restrict__ oh, fp16* __restrict__ ol){
    int m=blockIdx.x, tid=threadIdx.x;
    const float* row=x+(size_t)m*HID;
    float v0=row[tid], v1=row[tid+256], v2=row[tid+512];
    __shared__ float red[256];
    red[tid]=v0+v1+v2; __syncthreads();
    #pragma unroll
    for (int o=128;o>0;o>>=1){ if(tid<o) red[tid]+=red[tid+o]; __syncthreads(); }
    float mu=red[0]*(1.0f/768.0f); __syncthreads();
    float d0=v0-mu,d1=v1-mu,d2=v2-mu;
    red[tid]=d0*d0+d1*d1+d2*d2; __syncthreads();
    #pragma unroll
    for (int o=128;o>0;o>>=1){ if(tid<o) red[tid]+=red[tid+o]; __syncthreads(); }
    float rs=rsqrtf(red[0]*(1.0f/768.0f)+1e-5f);
    size_t base=(size_t)m*HID;
    #pragma unroll
    for (int j=0;j<3;j++){
        int col=tid+j*256;
        float dd=(j==0)?d0:(j==1)?d1:d2;
        float v=dd*rs*sc[col]+bi[col];
        fp16 h=__float2half(v);
        oh[base+col]=h; ol[base+col]=__float2half(v-__half2float(h));
    }
}

// ---- attention (fp32, fused qkv input, fp16-split output) ----
#define ATT_SMEMF (197*65*2 + 8*200 + 8*64)
__global__ __launch_bounds__(256) void attention_k(const float* __restrict__ qkv, fp16* __restrict__ oh, fp16* __restrict__ ol){
    extern __shared__ float s[];
    float* Kh=s; float* Vh=s+197*65; float* sr=Vh+197*65; float* qr=sr+8*200;
    int bh=blockIdx.x, b=bh/NH, h=bh%NH;
    int tid=threadIdx.x, wid=tid>>5, lane=tid&31;
    const float* kb=qkv+(size_t)(b*SEQ)*QKVW+HID+h*DH;
    const float* vb=qkv+(size_t)(b*SEQ)*QKVW+2*HID+h*DH;
    for (int idx=tid; idx<SEQ*DH; idx+=256){
        int t=idx>>6, dk=idx&63;
        Kh[t*65+dk]=kb[(size_t)t*QKVW+dk];
        Vh[t*65+dk]=vb[(size_t)t*QKVW+dk];
    }
    __syncthreads();
    const float* qb=qkv+(size_t)(b*SEQ)*QKVW+h*DH;
    size_t ob=(size_t)(b*SEQ)*HID+h*DH;
    float* myS=sr+wid*200; float* myQ=qr+wid*64;
    for (int sq=wid; sq<SEQ; sq+=8){
        myQ[lane]=qb[(size_t)sq*QKVW+lane];
        myQ[lane+32]=qb[(size_t)sq*QKVW+lane+32];
        __syncwarp();
        float scs[7], mx=-1e30f;
        #pragma unroll
        for (int i=0;i<7;i++){
            int t=lane+32*i; float d=-1e30f;
            if (t<SEQ){ d=0.f;
                #pragma unroll
                for (int dk=0;dk<64;dk++) d+=myQ[dk]*Kh[t*65+dk];
                d*=0.125f; }
            scs[i]=d; mx=fmaxf(mx,d);
        }
        #pragma unroll
        for (int o=16;o>0;o>>=1) mx=fmaxf(mx,__shfl_xor_sync(0xffffffffu,mx,o));
        float sum=0.f;
        #pragma unroll
        for (int i=0;i<7;i++){ int t=lane+32*i; float e=(t<SEQ)?expf(scs[i]-mx):0.f; scs[i]=e; sum+=e; }
        #pragma unroll
        for (int o=16;o>0;o>>=1) sum+=__shfl_xor_sync(0xffffffffu,sum,o);
        float inv=1.f/sum;
        #pragma unroll
        for (int i=0;i<7;i++){ int t=lane+32*i; if (t<SEQ) myS[t]=scs[i]*inv; }
        __syncwarp();
        float a0=0.f, a1=0.f;
        for (int t=0;t<SEQ;t++){ float p=myS[t]; a0+=p*Vh[t*65+lane]; a1+=p*Vh[t*65+lane+32]; }
        size_t o0=ob+(size_t)sq*HID+lane;
        fp16 h0=__float2half(a0), h1=__float2half(a1);
        oh[o0]=h0; oh[o0+32]=h1;
        ol[o0]=__float2half(a0-__half2float(h0));
        ol[o0+32]=__float2half(a1-__half2float(h1));
        __syncwarp();
    }
}

__global__ void head_k(const float* __restrict__ h, const float* __restrict__ W,
                       const float* __restrict__ bi, float* __restrict__ out){
    __shared__ float row[HID];
    int b=blockIdx.y, n=blockIdx.x*256+threadIdx.x;
    const float* hr=h+(size_t)(b*SEQ)*HID;
    for (int i=threadIdx.x;i<HID;i+=256) row[i]=hr[i];
    __syncthreads();
    if (n<NCLS){
        float acc=bi[n];
        for (int d=0;d<HID;d++) acc+=row[d]*W[(size_t)d*NCLS+n];
        out[(size_t)b*NCLS+n]=acc;
    }
}

template<typename T> static T* sym(const void* s){ void* p=nullptr; cudaGetSymbolAddress(&p,s); return (T*)p; }

extern "C" void kernel_launch(void* const* d_in, const int* in_sizes, int n_in, void* d_out, int out_size){
    const float *x=(const float*)d_in[0], *conv_w=(const float*)d_in[1], *conv_b=(const float*)d_in[2];
    const float *cls=(const float*)d_in[3], *pos=(const float*)d_in[4];
    const float *ln1_s=(const float*)d_in[5], *ln1_b=(const float*)d_in[6];
    const float *wq=(const float*)d_in[7], *bq=(const float*)d_in[8];
    const float *wk=(const float*)d_in[9], *bk=(const float*)d_in[10];
    const float *wv=(const float*)d_in[11], *bv=(const float*)d_in[12];
    const float *wo=(const float*)d_in[13], *bo=(const float*)d_in[14];
    const float *ln2_s=(const float*)d_in[15], *ln2_b=(const float*)d_in[16];
    const float *w1=(const float*)d_in[17], *b1=(const float*)d_in[18];
    const float *w2=(const float*)d_in[19], *b2=(const float*)d_in[20];
    const float *head_w=(const float*)d_in[21], *head_b=(const float*)d_in[22];
    float* out=(float*)d_out;

    float* h_  = sym<float>(g_h);
    float* qkv_= sym<float>(g_qkv);
    float* bq_ = sym<float>(g_bq);
    fp16 *hnh=sym<fp16>(g_hn_h), *hnl=sym<fp16>(g_hn_l);
    fp16 *ath=sym<fp16>(g_at_h), *atl=sym<fp16>(g_at_l);
    fp16 *m1h=sym<fp16>(g_m1_h), *m1l=sym<fp16>(g_m1_l);
    fp16 *xph=sym<fp16>(g_xp_h), *xpl=sym<fp16>(g_xp_l);
    fp16 *Wqh=sym<fp16>(g_Wq_h);
    fp16 *Woh=sym<fp16>(g_Wo_h);
    fp16 *W1h=sym<fp16>(g_W1_h);
    fp16 *W2h=sym<fp16>(g_W2_h);
    fp16 *Wph=sym<fp16>(g_Wp_h);

    cudaFuncSetAttribute(tc_gemm, cudaFuncAttributeMaxDynamicSharedMemorySize, GSMEM);
    cudaFuncSetAttribute(attention_k, cudaFuncAttributeMaxDynamicSharedMemorySize, ATT_SMEMF*(int)sizeof(float));

    dim3 tb(32,8);
    // order chosen so the ncu capture slot lands on tc_gemm
    patchify<<<(MPATCH*HID+255)/256,256>>>(x, xph, xpl);
    convWP_k<<<(HID*HID+255)/256,256>>>(conv_w, Wph);
    cbias_k<<<(NLAYER*QKVW+255)/256,256>>>(bq,bk,bv,bq_);
    tc_gemm<<<dim3(HID/BN,(MPATCH+BM-1)/BM),NTHR,GSMEM>>>(xph,xpl,Wph,MPATCH,HID,HID,conv_b,nullptr,qkv_,nullptr,nullptr,0);
    convQKV_k<<<dim3(24,72,12),tb>>>(wq,wk,wv,Wqh);
    convT_k<<<dim3(24,24,12),tb>>>(wo, Woh, HID, HID);
    convT_k<<<dim3(96,24,12),tb>>>(w1, W1h, HID, INTER);
    convT_k<<<dim3(24,96,12),tb>>>(w2, W2h, INTER, HID);
    build_h<<<(MTOK*HID+255)/256,256>>>(qkv_, cls, pos, h_);

    const int MT=(MTOK+BM-1)/BM;
    for (int l=0;l<NLAYER;l++){
        layernorm_k<<<MTOK,256>>>(h_, ln1_s+l*HID, ln1_b+l*HID, hnh, hnl);
        tc_gemm<<<dim3(QKVW/BN,MT),NTHR,GSMEM>>>(hnh,hnl,Wqh+(size_t)l*QKVW*HID,MTOK,QKVW,HID,bq_+l*QKVW,nullptr,qkv_,nullptr,nullptr,0);
        attention_k<<<BATCH*NH,256,ATT_SMEMF*(int)sizeof(float)>>>(qkv_, ath, atl);
        tc_gemm<<<dim3(HID/BN,MT),NTHR,GSMEM>>>(ath,atl,Woh+(size_t)l*HID*HID,MTOK,HID,HID,bo+l*HID,h_,h_,nullptr,nullptr,0);
        layernorm_k<<<MTOK,256>>>(h_, ln2_s+l*HID, ln2_b+l*HID, hnh, hnl);
        tc_gemm<<<dim3(INTER/BN,MT),NTHR,GSMEM>>>(hnh,hnl,W1h+(size_t)l*INTER*HID,MTOK,INTER,HID,b1+l*INTER,nullptr,nullptr,m1h,m1l,1);
        tc_gemm<<<dim3(HID/BN,MT),NTHR,GSMEM>>>(m1h,m1l,W2h+(size_t)l*HID*INTER,MTOK,HID,INTER,b2+l*HID,h_,h_,nullptr,nullptr,0);
    }
    head_k<<<dim3((NCLS+255)/256,BATCH),256>>>(h_, head_w, head_b, out);
}